// round 16
// baseline (speedup 1.0000x reference)
#include <cuda_runtime.h>
#include <cuda_fp16.h>
#include <math.h>
#include <stdint.h>

// ---------------------------------------------------------------------------
#define FDIM 128
#define DDEG 16
#define KH   2048
#define ODIM 256
#define JS   32
#define JCH  (KH/JS)   // 64

// Scratch (device globals; no allocation allowed)
__device__ float g_Mpart[JS][2][FDIM][ODIM];        // 8 MB partials
__device__ __align__(16) __half g_Bh[ODIM * 256];   // B[o][k] single fp16

// ---------------------------------------------------------------------------
// Kernel A: partial M[m][f][o] over a 64-wide j chunk
// ---------------------------------------------------------------------------
__global__ void __launch_bounds__(256)
kA(const float* __restrict__ R, const float* __restrict__ Ws,
   const float* __restrict__ Wn)
{
    __shared__ float sA[32][68];
    __shared__ float sB[32][68];

    const int ft = blockIdx.x, ot = blockIdx.y, mz = blockIdx.z;
    const int m = mz / JS, jc = mz % JS;
    const float* __restrict__ W = m ? Wn : Ws;
    const int f0 = ft * 64, o0 = ot * 64;
    const int jbase = jc * JCH;
    const int kk = jbase >> 8, hb = jbase & 255;
    const int tid = threadIdx.x, tx = tid & 15, ty = tid >> 4;

    float acc[4][4];
    #pragma unroll
    for (int i = 0; i < 4; i++)
        #pragma unroll
        for (int j = 0; j < 4; j++) acc[i][j] = 0.f;

    for (int jt = 0; jt < JCH; jt += 32) {
        #pragma unroll
        for (int r = 0; r < 2; r++) {
            int li = tid + r * 256;
            int f_l = li >> 3, jj = (li & 7) * 4;
            float4 a4 = *(const float4*)(R + (size_t)kk * (FDIM * 256)
                                           + (size_t)(f0 + f_l) * 256 + hb + jt + jj);
            sA[jj + 0][f_l] = a4.x; sA[jj + 1][f_l] = a4.y;
            sA[jj + 2][f_l] = a4.z; sA[jj + 3][f_l] = a4.w;
        }
        #pragma unroll
        for (int r = 0; r < 2; r++) {
            int li = tid + r * 256;
            int o_l = li >> 3, jj = (li & 7) * 4;
            float4 b4 = *(const float4*)(W + (size_t)(o0 + o_l) * KH + jbase + jt + jj);
            sB[jj + 0][o_l] = b4.x; sB[jj + 1][o_l] = b4.y;
            sB[jj + 2][o_l] = b4.z; sB[jj + 3][o_l] = b4.w;
        }
        __syncthreads();
        #pragma unroll
        for (int jj = 0; jj < 32; jj++) {
            float4 a4 = *(const float4*)&sA[jj][ty * 4];
            float4 b4 = *(const float4*)&sB[jj][tx * 4];
            float a[4] = {a4.x, a4.y, a4.z, a4.w};
            float b[4] = {b4.x, b4.y, b4.z, b4.w};
            #pragma unroll
            for (int i = 0; i < 4; i++)
                #pragma unroll
                for (int j = 0; j < 4; j++) acc[i][j] += a[i] * b[j];
        }
        __syncthreads();
    }
    float* outp = &g_Mpart[jc][m][0][0];
    #pragma unroll
    for (int i = 0; i < 4; i++) {
        float4 v = make_float4(acc[i][0], acc[i][1], acc[i][2], acc[i][3]);
        *(float4*)(outp + (size_t)(f0 + ty * 4 + i) * ODIM + o0 + tx * 4) = v;
    }
}

// Reduce partials -> single fp16 B[o][k], k = m*128+f.
__global__ void __launch_bounds__(256)
kReduce()
{
    int i = blockIdx.x * 256 + threadIdx.x;  // [m][f][o]
    const float* p = (const float*)g_Mpart;
    float s = 0.f;
    #pragma unroll
    for (int q = 0; q < JS; q++) s += p[(size_t)q * 2 * FDIM * ODIM + i];
    int m = i >> 15, f = (i >> 8) & 127, o = i & 255;
    int k = m * 128 + f;
    g_Bh[o * 256 + k] = __float2half_rn(s);
}

// ---------------------------------------------------------------------------
// kB_mma: persistent warp-specialized pipeline, 768 threads (24 warps/SM).
//   warps 0-15 (consumers): m16n32 tiles, ldmatrix + mma m16n8k16 f16.
//   warps 16-23 (producers): fp32 warp-cooperative gather, per-warp idx.
// ---------------------------------------------------------------------------
#define AS 264   // row stride (fp16 elems): 256 k + 8 pad, conflict-free LDSM

#define A_BUF  (64 * AS * 2)                   // 33792 per buffer (fp16 A)
#define SM_B   (2 * A_BUF)                     // 67584
#define SM_IX  (SM_B + 256 * AS * 2)           // 202752: single 4352 idx buffer
#define SM_TOT (SM_IX + 64 * 17 * 4)           // 207104 B -> 1 CTA/SM

// named barrier ids
#define BAR_FULL0  1
#define BAR_EMPTY0 3

#define BARSYNC(id, cnt) \
    asm volatile("bar.sync %0, %1;" :: "r"(id), "r"(cnt) : "memory")
#define BARARRIVE(id, cnt) \
    asm volatile("bar.arrive %0, %1;" :: "r"(id), "r"(cnt) : "memory")

__device__ __forceinline__ uint32_t s2u(const void* p) {
    uint32_t a;
    asm("{ .reg .u64 t; cvta.to.shared.u64 t, %1; cvt.u32.u64 %0, t; }"
        : "=r"(a) : "l"(p));
    return a;
}

#define LDSM4(r, addr) \
    asm volatile("ldmatrix.sync.aligned.m8n8.x4.shared.b16 {%0,%1,%2,%3}, [%4];" \
                 : "=r"((r)[0]), "=r"((r)[1]), "=r"((r)[2]), "=r"((r)[3]) \
                 : "r"(addr))

__device__ __forceinline__ void mma_f16(float* c, const uint32_t* a,
                                        uint32_t b0, uint32_t b1) {
    asm volatile(
        "mma.sync.aligned.m16n8k16.row.col.f32.f16.f16.f32 "
        "{%0,%1,%2,%3}, {%4,%5,%6,%7}, {%8,%9}, {%0,%1,%2,%3};"
        : "+f"(c[0]), "+f"(c[1]), "+f"(c[2]), "+f"(c[3])
        : "r"(a[0]), "r"(a[1]), "r"(a[2]), "r"(a[3]), "r"(b0), "r"(b1));
}

// pack 4 scaled floats into fp16 and store 8B
__device__ __forceinline__ void put4(__half* Ah, int off, float4 v, float s) {
    __half2 h01 = __floats2half2_rn(v.x * s, v.y * s);
    __half2 h23 = __floats2half2_rn(v.z * s, v.w * s);
    uint2 hp;
    hp.x = *(uint32_t*)&h01; hp.y = *(uint32_t*)&h23;
    *(uint2*)&Ah[off] = hp;
}

__global__ void __launch_bounds__(768, 1)
kB_mma(const float* __restrict__ x, const int* __restrict__ nbr,
       const float* __restrict__ bias, float* __restrict__ out, int N)
{
    extern __shared__ char smem[];
    const uint32_t sb = s2u(smem);
    const int tid = threadIdx.x;
    const int lane = tid & 31;
    const int NT = (N + 63) >> 6;
    const int G = gridDim.x;

    // --- stage B [256 o][256 k] fp16 into smem ONCE (all 768 threads) ---
    {
        const uint4* src = (const uint4*)g_Bh;
        for (int c = tid; c < 8192; c += 768) {
            int o = c >> 5, k8 = c & 31;
            *(uint4*)(smem + SM_B + (uint32_t)(o * (AS * 2) + k8 * 16)) = src[c];
        }
    }
    __syncthreads();

    if (tid >= 512) {
        // ===================== PRODUCER (warps 16..23) ====================
        const int pw = (tid >> 5) - 16;      // 0..7 -> nodes [pw*8, pw*8+8)
        int* sIdx = (int*)(smem + SM_IX);
        int i = 0;
        for (int tile = blockIdx.x; tile < NT; tile += G, i++) {
            const int p = i & 1;
            const int nb = tile * 64;
            __half* Ah = (__half*)(smem + p * A_BUF);

            // per-warp idx staging: this warp's 8 nodes x 16 neighbors
            #pragma unroll
            for (int r = 0; r < 4; r++) {
                int li = lane + r * 32;      // 0..127
                int nl = pw * 8 + (li >> 4), d = li & 15;
                int src = nb + nl; if (src >= N) src = N - 1;
                sIdx[nl * 17 + d] = nbr[(size_t)src * DDEG + d];
            }
            __syncwarp();

            if (i >= 2) BARSYNC(BAR_EMPTY0 + p, 768);  // buffer free?

            #pragma unroll 2
            for (int q = 0; q < 8; q++) {
                const int node = pw * 8 + q;
                const int* myidx = &sIdx[node * 17];
                int nsrc = nb + node; if (nsrc >= N) nsrc = N - 1;

                float4 a = make_float4(0.f, 0.f, 0.f, 0.f);
                #pragma unroll
                for (int d = 0; d < DDEG; d++) {
                    float4 v = *(const float4*)(x + (size_t)myidx[d] * FDIM + lane * 4);
                    a.x += v.x; a.y += v.y; a.z += v.z; a.w += v.w;
                }
                float4 sv = *(const float4*)(x + (size_t)nsrc * FDIM + lane * 4);

                put4(Ah, node * AS + 128 + lane * 4, a, 0.0625f); // nm
                put4(Ah, node * AS + lane * 4, sv, 1.0f);         // self
            }
            BARARRIVE(BAR_FULL0 + p, 768);   // A[p] full
        }
    } else {
        // ===================== CONSUMER (warps 0..15) =====================
        const int w = tid >> 5;              // 0..15
        const int g = lane >> 2, t = lane & 3;
        const int m0 = (w >> 2) * 16;        // 4 m-tiles of 16
        const int n0 = (w & 3) * 32;         // 4 n-tiles of 32

        const uint32_t aoff = (uint32_t)(((lane & 15) * AS + ((lane >> 4) << 3)) * 2);
        const uint32_t boff = (uint32_t)((((lane & 7) + ((lane >> 4) << 3)) * AS
                                          + (((lane >> 3) & 1) << 3)) * 2);

        int i = 0;
        for (int tile = blockIdx.x; tile < NT; tile += G, i++) {
            const int p = i & 1;
            const int nb = tile * 64;
            const uint32_t aBase = sb + (uint32_t)(p * A_BUF);

            BARSYNC(BAR_FULL0 + p, 768);     // wait A[p]

            #pragma unroll
            for (int oh = 0; oh < 2; oh++) {
                float acc[4][4];
                #pragma unroll
                for (int j = 0; j < 4; j++)
                    #pragma unroll
                    for (int c = 0; c < 4; c++) acc[j][c] = 0.f;

                const int o0 = oh * 128 + n0;

                #pragma unroll 4
                for (int ks = 0; ks < 16; ks++) {
                    const uint32_t kb = (uint32_t)(ks * 16 * 2);
                    uint32_t ah[4];
                    LDSM4(ah, aBase + (uint32_t)(m0 * AS * 2) + kb + aoff);
                    uint32_t bh[4][2];
                    #pragma unroll
                    for (int jp = 0; jp < 2; jp++) {
                        uint32_t base = (uint32_t)((o0 + jp * 16) * AS * 2) + kb + boff;
                        uint32_t tm[4];
                        LDSM4(tm, sb + SM_B + base);
                        bh[2 * jp][0] = tm[0]; bh[2 * jp][1] = tm[1];
                        bh[2 * jp + 1][0] = tm[2]; bh[2 * jp + 1][1] = tm[3];
                    }
                    #pragma unroll
                    for (int j = 0; j < 4; j++)
                        mma_f16(acc[j], ah, bh[j][0], bh[j][1]);
                }

                if (oh == 1) BARARRIVE(BAR_EMPTY0 + p, 768);  // A[p] free

                // epilogue (fast ELU, streaming stores keep x resident in L2)
                int node0 = nb + m0 + g;
                int node1 = node0 + 8;
                #pragma unroll
                for (int j = 0; j < 4; j++) {
                    int o = o0 + j * 8 + 2 * t;
                    float2 bv = *(const float2*)&bias[o];
                    if (node0 < N) {
                        float t0 = acc[j][0] + bv.x;
                        float t1 = acc[j][1] + bv.y;
                        float2 v;
                        v.x = (t0 > 0.f) ? t0 : (__expf(t0) - 1.0f);
                        v.y = (t1 > 0.f) ? t1 : (__expf(t1) - 1.0f);
                        __stcs((float2*)(out + (size_t)node0 * ODIM + o), v);
                    }
                    if (node1 < N) {
                        float t2 = acc[j][2] + bv.x;
                        float t3 = acc[j][3] + bv.y;
                        float2 v;
                        v.x = (t2 > 0.f) ? t2 : (__expf(t2) - 1.0f);
                        v.y = (t3 > 0.f) ? t3 : (__expf(t3) - 1.0f);
                        __stcs((float2*)(out + (size_t)node1 * ODIM + o), v);
                    }
                }
            }
        }
    }
}

// ---------------------------------------------------------------------------
extern "C" void kernel_launch(void* const* d_in, const int* in_sizes, int n_in,
                              void* d_out, int out_size)
{
    const float* x    = (const float*)d_in[0];
    const int*   nbr  = (const int*)  d_in[1];
    const float* R    = (const float*)d_in[2];
    const float* Ws   = (const float*)d_in[3];
    const float* Wn   = (const float*)d_in[4];
    const float* bias = (const float*)d_in[5];
    const int N = in_sizes[0] / FDIM;

    static int nsm = 0;
    if (nsm == 0) {
        cudaDeviceGetAttribute(&nsm, cudaDevAttrMultiProcessorCount, 0);
        if (nsm <= 0) nsm = 148;
        cudaFuncSetAttribute(kB_mma, cudaFuncAttributeMaxDynamicSharedMemorySize, SM_TOT);
    }

    kA<<<dim3(2, 4, 2 * JS), 256>>>(R, Ws, Wn);
    kReduce<<<(2 * FDIM * ODIM) / 256, 256>>>();
    kB_mma<<<nsm, 768, SM_TOT>>>(x, nbr, bias, (float*)d_out, N);
}

// round 17
// speedup vs baseline: 1.6549x; 1.6549x over previous
#include <cuda_runtime.h>
#include <cuda_fp16.h>
#include <math.h>
#include <stdint.h>

// ---------------------------------------------------------------------------
#define FDIM 128
#define DDEG 16
#define KH   2048
#define ODIM 256
#define JS   16
#define JCH  (KH/JS)

// Scratch (device globals; no allocation allowed)
__device__ float g_Mpart[JS][2][FDIM][ODIM];        // 4 MB partials
__device__ __align__(16) __half g_Bh[ODIM * 256];   // B[o][k] single fp16

// ---------------------------------------------------------------------------
// Kernel A: partial M[m][f][o] over a 128-wide j chunk (~14us)
// ---------------------------------------------------------------------------
__global__ void __launch_bounds__(256)
kA(const float* __restrict__ R, const float* __restrict__ Ws,
   const float* __restrict__ Wn)
{
    __shared__ float sA[32][68];
    __shared__ float sB[32][68];

    const int ft = blockIdx.x, ot = blockIdx.y, mz = blockIdx.z;
    const int m = mz / JS, jc = mz % JS;
    const float* __restrict__ W = m ? Wn : Ws;
    const int f0 = ft * 64, o0 = ot * 64;
    const int jbase = jc * JCH;
    const int kk = jbase >> 8, hb = jbase & 255;
    const int tid = threadIdx.x, tx = tid & 15, ty = tid >> 4;

    float acc[4][4];
    #pragma unroll
    for (int i = 0; i < 4; i++)
        #pragma unroll
        for (int j = 0; j < 4; j++) acc[i][j] = 0.f;

    for (int jt = 0; jt < JCH; jt += 32) {
        #pragma unroll
        for (int r = 0; r < 2; r++) {
            int li = tid + r * 256;
            int f_l = li >> 3, jj = (li & 7) * 4;
            float4 a4 = *(const float4*)(R + (size_t)kk * (FDIM * 256)
                                           + (size_t)(f0 + f_l) * 256 + hb + jt + jj);
            sA[jj + 0][f_l] = a4.x; sA[jj + 1][f_l] = a4.y;
            sA[jj + 2][f_l] = a4.z; sA[jj + 3][f_l] = a4.w;
        }
        #pragma unroll
        for (int r = 0; r < 2; r++) {
            int li = tid + r * 256;
            int o_l = li >> 3, jj = (li & 7) * 4;
            float4 b4 = *(const float4*)(W + (size_t)(o0 + o_l) * KH + jbase + jt + jj);
            sB[jj + 0][o_l] = b4.x; sB[jj + 1][o_l] = b4.y;
            sB[jj + 2][o_l] = b4.z; sB[jj + 3][o_l] = b4.w;
        }
        __syncthreads();
        #pragma unroll
        for (int jj = 0; jj < 32; jj++) {
            float4 a4 = *(const float4*)&sA[jj][ty * 4];
            float4 b4 = *(const float4*)&sB[jj][tx * 4];
            float a[4] = {a4.x, a4.y, a4.z, a4.w};
            float b[4] = {b4.x, b4.y, b4.z, b4.w};
            #pragma unroll
            for (int i = 0; i < 4; i++)
                #pragma unroll
                for (int j = 0; j < 4; j++) acc[i][j] += a[i] * b[j];
        }
        __syncthreads();
    }
    float* outp = &g_Mpart[jc][m][0][0];
    #pragma unroll
    for (int i = 0; i < 4; i++) {
        float4 v = make_float4(acc[i][0], acc[i][1], acc[i][2], acc[i][3]);
        *(float4*)(outp + (size_t)(f0 + ty * 4 + i) * ODIM + o0 + tx * 4) = v;
    }
}

// Reduce partials -> single fp16 B[o][k], k = m*128+f.
__global__ void __launch_bounds__(256)
kReduce()
{
    int i = blockIdx.x * 256 + threadIdx.x;  // [m][f][o]
    const float* p = (const float*)g_Mpart;
    float s = 0.f;
    #pragma unroll
    for (int q = 0; q < JS; q++) s += p[(size_t)q * 2 * FDIM * ODIM + i];
    int m = i >> 15, f = (i >> 8) & 127, o = i & 255;
    int k = m * 128 + f;
    g_Bh[o * 256 + k] = __float2half_rn(s);
}

// ---------------------------------------------------------------------------
// kB_mma: persistent warp-specialized pipeline, 1-pass fp16, B smem-resident.
//   warps 0-7  (consumers): single k-loop, A fragments reused for both halves.
//   warps 8-15 (producers): fp32 warp-cooperative gather, per-warp idx staging.
// ---------------------------------------------------------------------------
#define AS 264   // row stride (fp16 elems): 256 k + 8 pad, conflict-free LDSM

#define A_BUF  (64 * AS * 2)                   // 33792 per buffer (fp16 A)
#define SM_B   (2 * A_BUF)                     // 67584
#define SM_IX  (SM_B + 256 * AS * 2)           // 202752: single 4352 idx buffer
#define SM_TOT (SM_IX + 64 * 17 * 4)           // 207104 B -> 1 CTA/SM

// named barrier ids
#define BAR_FULL0  1
#define BAR_EMPTY0 3

#define BARSYNC(id, cnt) \
    asm volatile("bar.sync %0, %1;" :: "r"(id), "r"(cnt) : "memory")
#define BARARRIVE(id, cnt) \
    asm volatile("bar.arrive %0, %1;" :: "r"(id), "r"(cnt) : "memory")

__device__ __forceinline__ uint32_t s2u(const void* p) {
    uint32_t a;
    asm("{ .reg .u64 t; cvta.to.shared.u64 t, %1; cvt.u32.u64 %0, t; }"
        : "=r"(a) : "l"(p));
    return a;
}

#define LDSM4(r, addr) \
    asm volatile("ldmatrix.sync.aligned.m8n8.x4.shared.b16 {%0,%1,%2,%3}, [%4];" \
                 : "=r"((r)[0]), "=r"((r)[1]), "=r"((r)[2]), "=r"((r)[3]) \
                 : "r"(addr))

__device__ __forceinline__ void mma_f16(float* c, const uint32_t* a,
                                        uint32_t b0, uint32_t b1) {
    asm volatile(
        "mma.sync.aligned.m16n8k16.row.col.f32.f16.f16.f32 "
        "{%0,%1,%2,%3}, {%4,%5,%6,%7}, {%8,%9}, {%0,%1,%2,%3};"
        : "+f"(c[0]), "+f"(c[1]), "+f"(c[2]), "+f"(c[3])
        : "r"(a[0]), "r"(a[1]), "r"(a[2]), "r"(a[3]), "r"(b0), "r"(b1));
}

// pack 4 scaled floats into fp16 and store 8B
__device__ __forceinline__ void put4(__half* Ah, int off, float4 v, float s) {
    __half2 h01 = __floats2half2_rn(v.x * s, v.y * s);
    __half2 h23 = __floats2half2_rn(v.z * s, v.w * s);
    uint2 hp;
    hp.x = *(uint32_t*)&h01; hp.y = *(uint32_t*)&h23;
    *(uint2*)&Ah[off] = hp;
}

__global__ void __launch_bounds__(512, 1)
kB_mma(const float* __restrict__ x, const int* __restrict__ nbr,
       const float* __restrict__ bias, float* __restrict__ out, int N)
{
    extern __shared__ char smem[];
    const uint32_t sb = s2u(smem);
    const int tid = threadIdx.x;
    const int lane = tid & 31;
    const int NT = (N + 63) >> 6;
    const int G = gridDim.x;

    // --- stage B [256 o][256 k] fp16 into smem ONCE (all 512 threads) ---
    {
        const uint4* src = (const uint4*)g_Bh;
        #pragma unroll
        for (int r = 0; r < 16; r++) {
            int c = tid + r * 512;           // 0..8191 (16B units)
            int o = c >> 5, k8 = c & 31;
            *(uint4*)(smem + SM_B + (uint32_t)(o * (AS * 2) + k8 * 16)) = src[c];
        }
    }
    __syncthreads();

    if (tid >= 256) {
        // ===================== PRODUCER (warps 8..15) =====================
        const int pw = (tid >> 5) - 8;       // 0..7 -> nodes [pw*8, pw*8+8)
        int* sIdx = (int*)(smem + SM_IX);
        int i = 0;
        for (int tile = blockIdx.x; tile < NT; tile += G, i++) {
            const int p = i & 1;
            const int nb = tile * 64;
            __half* Ah = (__half*)(smem + p * A_BUF);

            // per-warp idx staging: this warp's 8 nodes x 16 neighbors
            #pragma unroll
            for (int r = 0; r < 4; r++) {
                int li = lane + r * 32;      // 0..127
                int nl = pw * 8 + (li >> 4), d = li & 15;
                int src = nb + nl; if (src >= N) src = N - 1;
                sIdx[nl * 17 + d] = nbr[(size_t)src * DDEG + d];
            }
            __syncwarp();

            if (i >= 2) BARSYNC(BAR_EMPTY0 + p, 512);  // buffer free?

            #pragma unroll 2
            for (int q = 0; q < 8; q++) {
                const int node = pw * 8 + q;
                const int* myidx = &sIdx[node * 17];
                int nsrc = nb + node; if (nsrc >= N) nsrc = N - 1;

                float4 a = make_float4(0.f, 0.f, 0.f, 0.f);
                #pragma unroll
                for (int d = 0; d < DDEG; d++) {
                    float4 v = *(const float4*)(x + (size_t)myidx[d] * FDIM + lane * 4);
                    a.x += v.x; a.y += v.y; a.z += v.z; a.w += v.w;
                }
                float4 sv = *(const float4*)(x + (size_t)nsrc * FDIM + lane * 4);

                put4(Ah, node * AS + 128 + lane * 4, a, 0.0625f); // nm
                put4(Ah, node * AS + lane * 4, sv, 1.0f);         // self
            }
            BARARRIVE(BAR_FULL0 + p, 512);   // A[p] full
        }
    } else {
        // ===================== CONSUMER (warps 0..7) ======================
        const int w = tid >> 5;              // 0..7
        const int g = lane >> 2, t = lane & 3;
        const int m0 = (w >> 2) * 32;
        const int n0 = (w & 3) * 32;

        const uint32_t aoff = (uint32_t)(((lane & 15) * AS + ((lane >> 4) << 3)) * 2);
        const uint32_t boff = (uint32_t)((((lane & 7) + ((lane >> 4) << 3)) * AS
                                          + (((lane >> 3) & 1) << 3)) * 2);

        int i = 0;
        for (int tile = blockIdx.x; tile < NT; tile += G, i++) {
            const int p = i & 1;
            const int nb = tile * 64;
            const uint32_t aBase = sb + (uint32_t)(p * A_BUF);

            BARSYNC(BAR_FULL0 + p, 512);     // wait A[p]

            // acc for BOTH output halves: [oh][mi][j][c] = 64 regs
            float acc[2][2][4][4];
            #pragma unroll
            for (int oh = 0; oh < 2; oh++)
                #pragma unroll
                for (int mi = 0; mi < 2; mi++)
                    #pragma unroll
                    for (int j = 0; j < 4; j++)
                        #pragma unroll
                        for (int c = 0; c < 4; c++) acc[oh][mi][j][c] = 0.f;

            // single k-loop: A fragments loaded once, used for both halves
            #pragma unroll 2
            for (int ks = 0; ks < 16; ks++) {
                const uint32_t kb = (uint32_t)(ks * 16 * 2);
                uint32_t ah[2][4];
                #pragma unroll
                for (int mi = 0; mi < 2; mi++) {
                    uint32_t base = (uint32_t)((m0 + mi * 16) * AS * 2) + kb + aoff;
                    LDSM4(ah[mi], aBase + base);
                }
                #pragma unroll
                for (int oh = 0; oh < 2; oh++) {
                    const int o0 = oh * 128 + n0;
                    uint32_t bh[4][2];
                    #pragma unroll
                    for (int jp = 0; jp < 2; jp++) {
                        uint32_t base = (uint32_t)((o0 + jp * 16) * AS * 2) + kb + boff;
                        uint32_t tm[4];
                        LDSM4(tm, sb + SM_B + base);
                        bh[2 * jp][0] = tm[0]; bh[2 * jp][1] = tm[1];
                        bh[2 * jp + 1][0] = tm[2]; bh[2 * jp + 1][1] = tm[3];
                    }
                    #pragma unroll
                    for (int j = 0; j < 4; j++)
                        #pragma unroll
                        for (int mi = 0; mi < 2; mi++)
                            mma_f16(acc[oh][mi][j], ah[mi], bh[j][0], bh[j][1]);
                }
            }

            BARARRIVE(BAR_EMPTY0 + p, 512);  // A[p] free (early release)

            // epilogue (fast ELU, streaming stores keep x resident in L2)
            #pragma unroll
            for (int oh = 0; oh < 2; oh++) {
                const int o0 = oh * 128 + n0;
                #pragma unroll
                for (int mi = 0; mi < 2; mi++) {
                    int node0 = nb + m0 + mi * 16 + g;
                    int node1 = node0 + 8;
                    #pragma unroll
                    for (int j = 0; j < 4; j++) {
                        int o = o0 + j * 8 + 2 * t;
                        float2 bv = *(const float2*)&bias[o];
                        if (node0 < N) {
                            float t0 = acc[oh][mi][j][0] + bv.x;
                            float t1 = acc[oh][mi][j][1] + bv.y;
                            float2 v;
                            v.x = (t0 > 0.f) ? t0 : (__expf(t0) - 1.0f);
                            v.y = (t1 > 0.f) ? t1 : (__expf(t1) - 1.0f);
                            __stcs((float2*)(out + (size_t)node0 * ODIM + o), v);
                        }
                        if (node1 < N) {
                            float t2 = acc[oh][mi][j][2] + bv.x;
                            float t3 = acc[oh][mi][j][3] + bv.y;
                            float2 v;
                            v.x = (t2 > 0.f) ? t2 : (__expf(t2) - 1.0f);
                            v.y = (t3 > 0.f) ? t3 : (__expf(t3) - 1.0f);
                            __stcs((float2*)(out + (size_t)node1 * ODIM + o), v);
                        }
                    }
                }
            }
        }
    }
}

// ---------------------------------------------------------------------------
extern "C" void kernel_launch(void* const* d_in, const int* in_sizes, int n_in,
                              void* d_out, int out_size)
{
    const float* x    = (const float*)d_in[0];
    const int*   nbr  = (const int*)  d_in[1];
    const float* R    = (const float*)d_in[2];
    const float* Ws   = (const float*)d_in[3];
    const float* Wn   = (const float*)d_in[4];
    const float* bias = (const float*)d_in[5];
    const int N = in_sizes[0] / FDIM;

    static int nsm = 0;
    if (nsm == 0) {
        cudaDeviceGetAttribute(&nsm, cudaDevAttrMultiProcessorCount, 0);
        if (nsm <= 0) nsm = 148;
        cudaFuncSetAttribute(kB_mma, cudaFuncAttributeMaxDynamicSharedMemorySize, SM_TOT);
    }

    kA<<<dim3(2, 4, 2 * JS), 256>>>(R, Ws, Wn);
    kReduce<<<(2 * FDIM * ODIM) / 256, 256>>>();
    kB_mma<<<nsm, 512, SM_TOT>>>(x, nbr, bias, (float*)d_out, N);
}